// round 7
// baseline (speedup 1.0000x reference)
#include <cuda_runtime.h>
#include <math.h>
#include <stdint.h>

#define TT 512
#define BB 64
#define DD 512
#define HH 512
#define GG 2048
#define KTOT 1024

typedef unsigned long long u64;

// ---------------- device scratch ----------------
__device__ float g_W[(size_t)GG * KTOT];        // 8 MB normalized weights
__device__ float g_zx[(size_t)TT * GG * BB];    // 256 MB x-projection (+bias)
__device__ float g_h[2][(size_t)HH * BB];       // h double buffer, [col][b]
__device__ unsigned g_bar_cnt;
__device__ unsigned g_bar_gen;

// ---------------- f32x2 helpers ----------------
__device__ __forceinline__ u64 pack2(float x, float y) {
    u64 r; asm("mov.b64 %0, {%1, %2};" : "=l"(r) : "f"(x), "f"(y)); return r;
}
__device__ __forceinline__ void fma2(u64& d, u64 a, u64 b) {
    asm("fma.rn.f32x2 %0, %1, %2, %0;" : "+l"(d) : "l"(a), "l"(b));
}
__device__ __forceinline__ float2 unpack2(u64 v) {
    float2 f; asm("mov.b64 {%0, %1}, %2;" : "=f"(f.x), "=f"(f.y) : "l"(v)); return f;
}

// ---------------- mbarrier + bulk-async helpers ----------------
__device__ __forceinline__ unsigned smem_u32(const void* p) {
    return (unsigned)__cvta_generic_to_shared(p);
}
__device__ __forceinline__ void mbar_init(unsigned mbar, unsigned count) {
    asm volatile("mbarrier.init.shared.b64 [%0], %1;" :: "r"(mbar), "r"(count) : "memory");
}
__device__ __forceinline__ void mbar_expect_tx(unsigned mbar, unsigned bytes) {
    asm volatile("mbarrier.arrive.expect_tx.shared.b64 _, [%0], %1;"
                 :: "r"(mbar), "r"(bytes) : "memory");
}
__device__ __forceinline__ void mbar_wait(unsigned mbar, unsigned parity) {
    unsigned done;
    asm volatile(
        "{\n\t.reg .pred p;\n\t"
        "mbarrier.try_wait.parity.acquire.cta.shared::cta.b64 p, [%1], %2;\n\t"
        "selp.b32 %0, 1, 0, p;\n\t}"
        : "=r"(done) : "r"(mbar), "r"(parity) : "memory");
    if (!done) {
        asm volatile(
            "{\n\t.reg .pred P1;\n\t"
            "WL_%=:\n\t"
            "mbarrier.try_wait.parity.acquire.cta.shared::cta.b64 P1, [%0], %1, 0x989680;\n\t"
            "@P1 bra.uni WD_%=;\n\t"
            "bra.uni WL_%=;\n\t"
            "WD_%=:\n\t}"
            :: "r"(mbar), "r"(parity) : "memory");
    }
}
__device__ __forceinline__ void bulk_g2s(unsigned smem_dst, const void* gsrc,
                                         unsigned bytes, unsigned mbar) {
    asm volatile(
        "cp.async.bulk.shared::cluster.global.mbarrier::complete_tx::bytes [%0], [%1], %2, [%3];"
        :: "r"(smem_dst), "l"(gsrc), "r"(bytes), "r"(mbar) : "memory");
}
__device__ __forceinline__ void fence_proxy_async_cta() {
    asm volatile("fence.proxy.async.shared::cta;" ::: "memory");
}

__device__ __forceinline__ unsigned ld_acq(unsigned* p) {
    unsigned v;
    asm volatile("ld.acquire.gpu.u32 %0, [%1];" : "=r"(v) : "l"(p) : "memory");
    return v;
}

__device__ __forceinline__ void grid_barrier(int nblocks) {
    __syncthreads();
    if (threadIdx.x == 0) {
        unsigned gen = ld_acq(&g_bar_gen);
        __threadfence();
        unsigned arrived = atomicAdd(&g_bar_cnt, 1u);
        if (arrived == (unsigned)(nblocks - 1)) {
            atomicExch(&g_bar_cnt, 0u);
            __threadfence();
            atomicAdd(&g_bar_gen, 1u);
        } else {
            while (ld_acq(&g_bar_gen) == gen) { __nanosleep(16); }
        }
        __threadfence();
    }
    __syncthreads();
}

__device__ __forceinline__ float sigf(float x) { return 1.0f / (1.0f + expf(-x)); }

// ============================================================================
// Phase 1: weight norm
// ============================================================================
__global__ __launch_bounds__(256) void qlstm_wnorm(const float* __restrict__ v,
                                                   const float* __restrict__ g) {
    int r = blockIdx.x;
    const float* vr = v + (size_t)r * KTOT;
    float s = 0.0f;
    for (int k = threadIdx.x; k < KTOT; k += 256) { float x = vr[k]; s += x * x; }
    __shared__ float red[256];
    red[threadIdx.x] = s;
    __syncthreads();
    for (int off = 128; off > 0; off >>= 1) {
        if (threadIdx.x < off) red[threadIdx.x] += red[threadIdx.x + off];
        __syncthreads();
    }
    float scale = g[r] * rsqrtf(red[0]);
    for (int k = threadIdx.x; k < KTOT; k += 256)
        g_W[(size_t)r * KTOT + k] = vr[k] * scale;
}

// ============================================================================
// Phase 2: zx = X @ Wx^T + bias.  CTA 128r x 128n, thread tile 8r x 8n.
// ============================================================================
#define AST_PAD 132
#define BSS_PAD 132

__global__ __launch_bounds__(256) void qlstm_gemm_x(const float* __restrict__ X,
                                                    const float* __restrict__ bias) {
    __shared__ float Ast[16 * AST_PAD];   // [k][r]
    __shared__ float Bs[16 * BSS_PAD];    // [k][n]

    const int rt  = blockIdx.x * 128;
    const int nt  = blockIdx.y * 128;
    const int tid = threadIdx.x;
    const int rg  = tid >> 4;
    const int ng  = tid & 15;
    const int r0  = rg * 8;
    const int n0  = ng * 8;

    u64 acc[8][4];
    #pragma unroll
    for (int i = 0; i < 8; i++)
        #pragma unroll
        for (int j = 0; j < 4; j++) acc[i][j] = 0ULL;

    for (int kt = 0; kt < DD; kt += 16) {
        __syncthreads();
        #pragma unroll
        for (int u = 0; u < 2; u++) {
            int idx = tid + u * 256;
            int r = idx >> 2, kq = (idx & 3) << 2;
            float4 va = *(const float4*)(g_W + (size_t)(rt + r) * KTOT + kt + kq);
            Ast[(kq + 0) * AST_PAD + r] = va.x;
            Ast[(kq + 1) * AST_PAD + r] = va.y;
            Ast[(kq + 2) * AST_PAD + r] = va.z;
            Ast[(kq + 3) * AST_PAD + r] = va.w;
        }
        #pragma unroll
        for (int u = 0; u < 2; u++) {
            int idx = tid + u * 256;
            int n = idx >> 2, kq = (idx & 3) << 2;
            float4 vb = *(const float4*)(X + (size_t)(nt + n) * DD + kt + kq);
            Bs[(kq + 0) * BSS_PAD + n] = vb.x;
            Bs[(kq + 1) * BSS_PAD + n] = vb.y;
            Bs[(kq + 2) * BSS_PAD + n] = vb.z;
            Bs[(kq + 3) * BSS_PAD + n] = vb.w;
        }
        __syncthreads();

        #pragma unroll
        for (int kk = 0; kk < 16; kk++) {
            ulonglong2 b01 = *(const ulonglong2*)&Bs[kk * BSS_PAD + n0];
            ulonglong2 b23 = *(const ulonglong2*)&Bs[kk * BSS_PAD + n0 + 4];
            float4 w0 = *(const float4*)&Ast[kk * AST_PAD + r0];
            float4 w1 = *(const float4*)&Ast[kk * AST_PAD + r0 + 4];
            float wv[8] = {w0.x, w0.y, w0.z, w0.w, w1.x, w1.y, w1.z, w1.w};
            #pragma unroll
            for (int i = 0; i < 8; i++) {
                u64 wd = pack2(wv[i], wv[i]);
                fma2(acc[i][0], wd, b01.x); fma2(acc[i][1], wd, b01.y);
                fma2(acc[i][2], wd, b23.x); fma2(acc[i][3], wd, b23.y);
            }
        }
    }

    const int t  = blockIdx.y * 2 + (n0 >> 6);
    const int b0 = n0 & 63;
    #pragma unroll
    for (int i = 0; i < 8; i++) {
        int r = rt + r0 + i;
        float bi = bias[r];
        float2 p0 = unpack2(acc[i][0]);
        float2 p1 = unpack2(acc[i][1]);
        float2 p2 = unpack2(acc[i][2]);
        float2 p3 = unpack2(acc[i][3]);
        float* dst = g_zx + ((size_t)t * GG + r) * BB + b0;
        *(float4*)dst       = make_float4(p0.x + bi, p0.y + bi, p1.x + bi, p1.y + bi);
        *(float4*)(dst + 4) = make_float4(p2.x + bi, p2.y + bi, p3.x + bi, p3.y + bi);
    }
}

// ============================================================================
// Phase 3: persistent recurrence. 128 CTAs x 256 thr = 8 warps.
// h staged via cp.async.bulk (8 x 16KB, one mbarrier per warp slice);
// zx staged via bulk on 2 step-alternating mbarriers. FFMA2 k-loop unchanged.
// ============================================================================
#define P3_NCTA 128
#define WS_PAD 516
#define OFF_HS   (16 * WS_PAD * 4)           // 33024
#define OFF_ZSP  (OFF_HS + 131072)           // 164096
#define OFF_ZXS  (OFF_ZSP + 32768)           // 196864
#define OFF_MBAR (OFF_ZXS + 8192)            // 205056 (8 h-mbars + 2 zx-mbars)
#define SM_BYTES (OFF_MBAR + 128)            // 205184

__global__ __launch_bounds__(256) void qlstm_recur(float* __restrict__ out, int out_size) {
    extern __shared__ unsigned char smraw[];
    float* Wsf = (float*)smraw;                     // [16][516] non-dup
    float* hs  = (float*)(smraw + OFF_HS);          // [512][64]
    float* zsp = (float*)(smraw + OFF_ZSP);         // [8 ks][16][64]
    float* zxs = (float*)(smraw + OFF_ZXS);         // [2][16][64]
    u64*   mbars = (u64*)(smraw + OFF_MBAR);

    const int tid = threadIdx.x;
    const int bc  = blockIdx.x;
    const int c0  = bc * 4;
    const unsigned mb_h0  = smem_u32(&mbars[0]);    // +8*i
    const unsigned mb_zx0 = smem_u32(&mbars[8]);    // +8*i

    // init mbarriers (every launch / graph replay)
    if (tid == 0) {
        #pragma unroll
        for (int i = 0; i < 10; i++) mbar_init(smem_u32(&mbars[i]), 1);
    }
    __syncthreads();
    fence_proxy_async_cta();
    __syncthreads();

    // load weight slice (non-duplicated)
    #pragma unroll
    for (int u = 0; u < 32; u++) {
        int idx = tid + u * 256;
        int lr = idx >> 9, k = idx & 511;
        int gr = (lr >> 2) * 512 + c0 + (lr & 3);
        Wsf[lr * WS_PAD + k] = g_W[(size_t)gr * KTOT + 512 + k];
    }

    // pre-loop: issue zx[0] fill (4 gates x 1KB contiguous) on mb_zx[0]
    if (tid == 0) {
        mbar_expect_tx(mb_zx0, 4096);
        #pragma unroll
        for (int gi = 0; gi < 4; gi++)
            bulk_g2s(smem_u32(zxs + gi * 256),
                     g_zx + ((size_t)gi * 512 + c0) * BB, 1024, mb_zx0);
    }

    // zero h buffer 0 + c state
    const int ep_j = tid >> 6, ep_b = tid & 63;
    g_h[0][(size_t)(c0 + ep_j) * BB + ep_b] = 0.0f;
    float creg = 0.0f, hlast = 0.0f;
    __threadfence();
    grid_barrier(P3_NCTA);

    const int ks    = tid >> 5;          // warp = k-split (64 k)
    const int rgi   = (tid >> 4) & 1;    // row interleave bit
    const int b0    = (tid & 15) * 4;
    const int kbase = ks * 64;
    const unsigned mb_mine = mb_h0 + ks * 8;

    for (int s = 0; s < TT; s++) {
        const float* hsrc = g_h[s & 1];

        if (tid == 0) {
            // zx fill for step s+1 on alternating barrier
            if (s + 1 < TT) {
                unsigned mz = mb_zx0 + ((s + 1) & 1) * 8;
                float* zdst = zxs + ((s + 1) & 1) * 1024;
                mbar_expect_tx(mz, 4096);
                #pragma unroll
                for (int gi = 0; gi < 4; gi++)
                    bulk_g2s(smem_u32(zdst + gi * 256),
                             g_zx + ((size_t)(s + 1) * GG + (size_t)gi * 512 + c0) * BB,
                             1024, mz);
            }
            // 8 h-slice bulk copies (16KB each)
            #pragma unroll
            for (int w = 0; w < 8; w++) {
                unsigned m = mb_h0 + w * 8;
                mbar_expect_tx(m, 16384);
                bulk_g2s(smem_u32(hs + w * 4096), hsrc + w * 4096, 16384, m);
            }
        }

        // wait for my warp's slice
        mbar_wait(mb_mine, s & 1);

        u64 acc[8][2];
        #pragma unroll
        for (int r = 0; r < 8; r++) { acc[r][0] = 0ULL; acc[r][1] = 0ULL; }

        const float* hbase = hs + kbase * 64 + b0;
        const float* wbase = Wsf + rgi * WS_PAD + kbase;

        #pragma unroll 4
        for (int kb = 0; kb < 16; kb++) {
            ulonglong2 hq[4];
            #pragma unroll
            for (int j = 0; j < 4; j++)
                hq[j] = *(const ulonglong2*)(hbase + (kb * 4 + j) * 64);
            #pragma unroll
            for (int rr = 0; rr < 8; rr++) {
                float4 wv = *(const float4*)(wbase + rr * 2 * WS_PAD + kb * 4);
                u64 w0 = pack2(wv.x, wv.x), w1 = pack2(wv.y, wv.y);
                u64 w2 = pack2(wv.z, wv.z), w3 = pack2(wv.w, wv.w);
                fma2(acc[rr][0], w0, hq[0].x); fma2(acc[rr][1], w0, hq[0].y);
                fma2(acc[rr][0], w1, hq[1].x); fma2(acc[rr][1], w1, hq[1].y);
                fma2(acc[rr][0], w2, hq[2].x); fma2(acc[rr][1], w2, hq[2].y);
                fma2(acc[rr][0], w3, hq[3].x); fma2(acc[rr][1], w3, hq[3].y);
            }
        }

        // write k-split partials
        #pragma unroll
        for (int rr = 0; rr < 8; rr++) {
            int lr = rr * 2 + rgi;
            float2 a = unpack2(acc[rr][0]);
            float2 c2 = unpack2(acc[rr][1]);
            *(float4*)&zsp[(ks * 16 + lr) * 64 + b0] = make_float4(a.x, a.y, c2.x, c2.y);
        }
        __syncthreads();

        // gate epilogue (wait zx for this step: barrier s&1, phase (s>>1)&1)
        mbar_wait(mb_zx0 + (s & 1) * 8, (s >> 1) & 1);
        float z[4];
        #pragma unroll
        for (int gi = 0; gi < 4; gi++) {
            int row = gi * 4 + ep_j;
            float ssum = zxs[(s & 1) * 1024 + row * 64 + ep_b];
            #pragma unroll
            for (int q = 0; q < 8; q++)
                ssum += zsp[(q * 16 + row) * 64 + ep_b];
            z[gi] = ssum;
        }
        float fg = sigf(z[0]), ig = sigf(z[1]), ug = tanhf(z[2]), og = sigf(z[3]);
        creg = fg * creg + ig * ug;
        float hv = og * tanhf(creg);
        hlast = hv;
        g_h[(s + 1) & 1][(size_t)(c0 + ep_j) * BB + ep_b] = hv;
        out[((size_t)s * BB + ep_b) * HH + c0 + ep_j] = hv;

        grid_barrier(P3_NCTA);
    }

    size_t TBH = (size_t)TT * BB * HH;
    if ((size_t)out_size >= TBH + 2 * (size_t)BB * HH) {
        out[TBH + (size_t)ep_b * HH + c0 + ep_j] = hlast;
        out[TBH + (size_t)BB * HH + (size_t)ep_b * HH + c0 + ep_j] = creg;
    }
}

extern "C" void kernel_launch(void* const* d_in, const int* in_sizes, int n_in,
                              void* d_out, int out_size) {
    const float* X  = (const float*)d_in[0];
    const float* v  = (const float*)d_in[1];
    const float* g  = (const float*)d_in[2];
    const float* b  = (const float*)d_in[3];
    float* out = (float*)d_out;

    cudaFuncSetAttribute(qlstm_recur, cudaFuncAttributeMaxDynamicSharedMemorySize, SM_BYTES);

    qlstm_wnorm<<<GG, 256>>>(v, g);
    qlstm_gemm_x<<<dim3(GG / 128, TT / 2), 256>>>(X, b);
    qlstm_recur<<<P3_NCTA, 256, SM_BYTES>>>(out, out_size);
}

// round 8
// speedup vs baseline: 1.0214x; 1.0214x over previous
#include <cuda_runtime.h>
#include <math.h>
#include <stdint.h>

#define TT 512
#define BB 64
#define DD 512
#define HH 512
#define GG 2048
#define KTOT 1024

typedef unsigned long long u64;

// ---------------- device scratch ----------------
__device__ float g_W[(size_t)GG * KTOT];          // 8 MB normalized weights
// zx layout: [t][cb 32][bg 4][64 rows (gate*16+cloc)][16 b]
__device__ float g_zx[(size_t)TT * 32 * 4 * 64 * 16];
__device__ float g_hG[4][2][512 * 16];            // [group][parity][col*16+b]
__device__ unsigned g_cnt4[4 * 32];               // group barrier counters (padded)
__device__ unsigned g_gen4[4 * 32];

// ---------------- f32x2 helpers ----------------
__device__ __forceinline__ u64 pack2(float x, float y) {
    u64 r; asm("mov.b64 %0, {%1, %2};" : "=l"(r) : "f"(x), "f"(y)); return r;
}
__device__ __forceinline__ void fma2(u64& d, u64 a, u64 b) {
    asm("fma.rn.f32x2 %0, %1, %2, %0;" : "+l"(d) : "l"(a), "l"(b));
}
__device__ __forceinline__ float2 unpack2(u64 v) {
    float2 f; asm("mov.b64 {%0, %1}, %2;" : "=f"(f.x), "=f"(f.y) : "l"(v)); return f;
}

// ---------------- mbarrier + bulk-async helpers ----------------
__device__ __forceinline__ unsigned smem_u32(const void* p) {
    return (unsigned)__cvta_generic_to_shared(p);
}
__device__ __forceinline__ void mbar_init(unsigned mbar, unsigned count) {
    asm volatile("mbarrier.init.shared.b64 [%0], %1;" :: "r"(mbar), "r"(count) : "memory");
}
__device__ __forceinline__ void mbar_expect_tx(unsigned mbar, unsigned bytes) {
    asm volatile("mbarrier.arrive.expect_tx.shared.b64 _, [%0], %1;"
                 :: "r"(mbar), "r"(bytes) : "memory");
}
__device__ __forceinline__ void mbar_wait(unsigned mbar, unsigned parity) {
    unsigned done;
    asm volatile(
        "{\n\t.reg .pred p;\n\t"
        "mbarrier.try_wait.parity.acquire.cta.shared::cta.b64 p, [%1], %2;\n\t"
        "selp.b32 %0, 1, 0, p;\n\t}"
        : "=r"(done) : "r"(mbar), "r"(parity) : "memory");
    if (!done) {
        asm volatile(
            "{\n\t.reg .pred P1;\n\t"
            "WL_%=:\n\t"
            "mbarrier.try_wait.parity.acquire.cta.shared::cta.b64 P1, [%0], %1, 0x989680;\n\t"
            "@P1 bra.uni WD_%=;\n\t"
            "bra.uni WL_%=;\n\t"
            "WD_%=:\n\t}"
            :: "r"(mbar), "r"(parity) : "memory");
    }
}
__device__ __forceinline__ void bulk_g2s(unsigned smem_dst, const void* gsrc,
                                         unsigned bytes, unsigned mbar) {
    asm volatile(
        "cp.async.bulk.shared::cluster.global.mbarrier::complete_tx::bytes [%0], [%1], %2, [%3];"
        :: "r"(smem_dst), "l"(gsrc), "r"(bytes), "r"(mbar) : "memory");
}
__device__ __forceinline__ void fence_proxy_async_cta() {
    asm volatile("fence.proxy.async.shared::cta;" ::: "memory");
}
__device__ __forceinline__ unsigned ld_acq(unsigned* p) {
    unsigned v;
    asm volatile("ld.acquire.gpu.u32 %0, [%1];" : "=r"(v) : "l"(p) : "memory");
    return v;
}

__device__ __forceinline__ void group_barrier(unsigned* cnt, unsigned* gen, int nblocks) {
    __syncthreads();
    if (threadIdx.x == 0) {
        unsigned g0 = ld_acq(gen);
        __threadfence();
        unsigned arrived = atomicAdd(cnt, 1u);
        if (arrived == (unsigned)(nblocks - 1)) {
            atomicExch(cnt, 0u);
            __threadfence();
            atomicAdd(gen, 1u);
        } else {
            while (ld_acq(gen) == g0) { __nanosleep(16); }
        }
        __threadfence();
    }
    __syncthreads();
}

__device__ __forceinline__ float sigf(float x) { return 1.0f / (1.0f + expf(-x)); }

// ============================================================================
// Phase 1: weight norm
// ============================================================================
__global__ __launch_bounds__(256) void qlstm_wnorm(const float* __restrict__ v,
                                                   const float* __restrict__ g) {
    int r = blockIdx.x;
    const float* vr = v + (size_t)r * KTOT;
    float s = 0.0f;
    for (int k = threadIdx.x; k < KTOT; k += 256) { float x = vr[k]; s += x * x; }
    __shared__ float red[256];
    red[threadIdx.x] = s;
    __syncthreads();
    for (int off = 128; off > 0; off >>= 1) {
        if (threadIdx.x < off) red[threadIdx.x] += red[threadIdx.x + off];
        __syncthreads();
    }
    float scale = g[r] * rsqrtf(red[0]);
    for (int k = threadIdx.x; k < KTOT; k += 256)
        g_W[(size_t)r * KTOT + k] = vr[k] * scale;
}

// ============================================================================
// Phase 2: zx = X @ Wx^T + bias, stored in grouped layout.
// CTA 128r x 128n, thread tile 8r x 8n.
// ============================================================================
#define AST_PAD 132
#define BSS_PAD 132

__global__ __launch_bounds__(256) void qlstm_gemm_x(const float* __restrict__ X,
                                                    const float* __restrict__ bias) {
    __shared__ float Ast[16 * AST_PAD];   // [k][r]
    __shared__ float Bs[16 * BSS_PAD];    // [k][n]

    const int rt  = blockIdx.x * 128;
    const int nt  = blockIdx.y * 128;
    const int tid = threadIdx.x;
    const int rg  = tid >> 4;
    const int ng  = tid & 15;
    const int r0  = rg * 8;
    const int n0  = ng * 8;

    u64 acc[8][4];
    #pragma unroll
    for (int i = 0; i < 8; i++)
        #pragma unroll
        for (int j = 0; j < 4; j++) acc[i][j] = 0ULL;

    for (int kt = 0; kt < DD; kt += 16) {
        __syncthreads();
        #pragma unroll
        for (int u = 0; u < 2; u++) {
            int idx = tid + u * 256;
            int r = idx >> 2, kq = (idx & 3) << 2;
            float4 va = *(const float4*)(g_W + (size_t)(rt + r) * KTOT + kt + kq);
            Ast[(kq + 0) * AST_PAD + r] = va.x;
            Ast[(kq + 1) * AST_PAD + r] = va.y;
            Ast[(kq + 2) * AST_PAD + r] = va.z;
            Ast[(kq + 3) * AST_PAD + r] = va.w;
        }
        #pragma unroll
        for (int u = 0; u < 2; u++) {
            int idx = tid + u * 256;
            int n = idx >> 2, kq = (idx & 3) << 2;
            float4 vb = *(const float4*)(X + (size_t)(nt + n) * DD + kt + kq);
            Bs[(kq + 0) * BSS_PAD + n] = vb.x;
            Bs[(kq + 1) * BSS_PAD + n] = vb.y;
            Bs[(kq + 2) * BSS_PAD + n] = vb.z;
            Bs[(kq + 3) * BSS_PAD + n] = vb.w;
        }
        __syncthreads();

        #pragma unroll
        for (int kk = 0; kk < 16; kk++) {
            ulonglong2 b01 = *(const ulonglong2*)&Bs[kk * BSS_PAD + n0];
            ulonglong2 b23 = *(const ulonglong2*)&Bs[kk * BSS_PAD + n0 + 4];
            float4 w0 = *(const float4*)&Ast[kk * AST_PAD + r0];
            float4 w1 = *(const float4*)&Ast[kk * AST_PAD + r0 + 4];
            float wv[8] = {w0.x, w0.y, w0.z, w0.w, w1.x, w1.y, w1.z, w1.w};
            #pragma unroll
            for (int i = 0; i < 8; i++) {
                u64 wd = pack2(wv[i], wv[i]);
                fma2(acc[i][0], wd, b01.x); fma2(acc[i][1], wd, b01.y);
                fma2(acc[i][2], wd, b23.x); fma2(acc[i][3], wd, b23.y);
            }
        }
    }

    const int t  = blockIdx.y * 2 + (n0 >> 6);
    const int b0 = n0 & 63;
    const int bg = b0 >> 4;
    const int bi = b0 & 15;         // 0 or 8; both float4s stay inside 16-b slab
    #pragma unroll
    for (int i = 0; i < 8; i++) {
        int r = rt + r0 + i;
        int gate = r >> 9, col = r & 511;
        int cb = col >> 4, cloc = col & 15;
        float bi_f = bias[r];
        float2 p0 = unpack2(acc[i][0]);
        float2 p1 = unpack2(acc[i][1]);
        float2 p2 = unpack2(acc[i][2]);
        float2 p3 = unpack2(acc[i][3]);
        float* dst = g_zx + (((size_t)t * 32 + cb) * 4 + bg) * 1024
                   + (gate * 16 + cloc) * 16 + bi;
        *(float4*)dst       = make_float4(p0.x + bi_f, p0.y + bi_f, p1.x + bi_f, p1.y + bi_f);
        *(float4*)(dst + 4) = make_float4(p2.x + bi_f, p2.y + bi_f, p3.x + bi_f, p3.y + bi_f);
    }
}

// ============================================================================
// Phase 3: persistent recurrence, 4 independent batch groups of 32 CTAs.
// CTA owns 16 h-cols x 4 gates (64 rows) x 16 batches. Weights 132KB in smem.
// ============================================================================
#define P3_NCTA 128
#define WS_PAD 516
#define OFF_HS   (64 * WS_PAD * 4)           // 132096
#define OFF_ZSP  (OFF_HS + 32768)            // 164864
#define OFF_ZXS  (OFF_ZSP + 32768)           // 197632
#define OFF_MBAR (OFF_ZXS + 8192)            // 205824
#define SM_BYTES (OFF_MBAR + 128)            // 205952

__global__ __launch_bounds__(256) void qlstm_recur(float* __restrict__ out, int out_size) {
    extern __shared__ unsigned char smraw[];
    float* Wsf = (float*)smraw;                     // [64][516]
    float* hs  = (float*)(smraw + OFF_HS);          // [512 k][16 b]
    float* zsp = (float*)(smraw + OFF_ZSP);         // [8 ks][64 r][16 b]
    float* zxs = (float*)(smraw + OFF_ZXS);         // [2][64 r][16 b]
    u64*   mbars = (u64*)(smraw + OFF_MBAR);

    const int tid = threadIdx.x;
    const int bc  = blockIdx.x;
    const int bg  = bc >> 5;                 // batch group 0..3
    const int cb  = bc & 31;                 // col block 0..31
    const int c0  = cb * 16;
    const unsigned mb_h0  = smem_u32(&mbars[0]);
    const unsigned mb_zx0 = smem_u32(&mbars[8]);

    if (tid == 0) {
        #pragma unroll
        for (int i = 0; i < 10; i++) mbar_init(smem_u32(&mbars[i]), 1);
    }
    __syncthreads();
    fence_proxy_async_cta();
    __syncthreads();

    // load weight slice: 64 rows (gate*16+cloc) x 512 k
    #pragma unroll
    for (int u = 0; u < 32; u++) {
        int idx = tid + u * 256;             // 0..8191 float4 slots
        int lr = idx >> 7, kq = (idx & 127) << 2;
        int gate = lr >> 4, cloc = lr & 15;
        int gr = gate * 512 + c0 + cloc;
        *(float4*)&Wsf[lr * WS_PAD + kq] =
            *(const float4*)(g_W + (size_t)gr * KTOT + 512 + kq);
    }

    // issue zx[0] (one 4KB contiguous slice)
    const size_t zx_cta = ((size_t)cb * 4 + bg) * 1024;
    if (tid == 0) {
        mbar_expect_tx(mb_zx0, 4096);
        bulk_g2s(smem_u32(zxs), g_zx + zx_cta, 4096, mb_zx0);
    }

    // zero h[0] for own cols + init c
    const int ep_c = tid >> 4;               // 0..15 local col
    const int ep_b = tid & 15;               // 0..15 local batch
    g_hG[bg][0][(c0 + ep_c) * 16 + ep_b] = 0.0f;
    float creg = 0.0f, hlast = 0.0f;
    unsigned* bcnt = &g_cnt4[bg * 32];
    unsigned* bgen = &g_gen4[bg * 32];
    __threadfence();
    group_barrier(bcnt, bgen, 32);

    const int ks    = tid >> 5;              // warp k-slice (64 k)
    const int lane  = tid & 31;
    const int rq    = lane >> 2;             // rows rq, rq+8, ..., rq+56
    const int pq    = lane & 3;              // b offset pq*4 (2 f32x2 pairs)
    const int kbase = ks * 64;
    const unsigned mb_mine = mb_h0 + ks * 8;

    for (int s = 0; s < TT; s++) {
        const float* hsrc = g_hG[bg][s & 1];

        if (tid == 0) {
            if (s + 1 < TT) {
                unsigned mz = mb_zx0 + ((s + 1) & 1) * 8;
                mbar_expect_tx(mz, 4096);
                bulk_g2s(smem_u32(zxs + ((s + 1) & 1) * 1024),
                         g_zx + (size_t)(s + 1) * 131072 + zx_cta, 4096, mz);
            }
            #pragma unroll
            for (int w = 0; w < 8; w++) {
                unsigned m = mb_h0 + w * 8;
                mbar_expect_tx(m, 4096);
                bulk_g2s(smem_u32(hs + w * 1024), hsrc + w * 1024, 4096, m);
            }
        }

        mbar_wait(mb_mine, s & 1);

        u64 acc[8][2];
        #pragma unroll
        for (int j = 0; j < 8; j++) { acc[j][0] = 0ULL; acc[j][1] = 0ULL; }

        const float* hb = hs + kbase * 16 + pq * 4;
        const float* wb = Wsf + rq * WS_PAD + kbase;

        #pragma unroll 2
        for (int kb = 0; kb < 16; kb++) {
            ulonglong2 hq[4];
            #pragma unroll
            for (int kk = 0; kk < 4; kk++)
                hq[kk] = *(const ulonglong2*)(hb + (kb * 4 + kk) * 16);
            #pragma unroll
            for (int j = 0; j < 8; j++) {
                float4 wv = *(const float4*)(wb + j * 8 * WS_PAD + kb * 4);
                u64 w0 = pack2(wv.x, wv.x), w1 = pack2(wv.y, wv.y);
                u64 w2 = pack2(wv.z, wv.z), w3 = pack2(wv.w, wv.w);
                fma2(acc[j][0], w0, hq[0].x); fma2(acc[j][1], w0, hq[0].y);
                fma2(acc[j][0], w1, hq[1].x); fma2(acc[j][1], w1, hq[1].y);
                fma2(acc[j][0], w2, hq[2].x); fma2(acc[j][1], w2, hq[2].y);
                fma2(acc[j][0], w3, hq[3].x); fma2(acc[j][1], w3, hq[3].y);
            }
        }

        // write k-split partials: zsp[ks][row][b]
        #pragma unroll
        for (int j = 0; j < 8; j++) {
            int row = rq + j * 8;
            float2 a = unpack2(acc[j][0]);
            float2 c2 = unpack2(acc[j][1]);
            *(float4*)&zsp[(ks * 64 + row) * 16 + pq * 4] =
                make_float4(a.x, a.y, c2.x, c2.y);
        }
        __syncthreads();

        // epilogue: thread (ep_c, ep_b)
        mbar_wait(mb_zx0 + (s & 1) * 8, (s >> 1) & 1);
        float z[4];
        #pragma unroll
        for (int gi = 0; gi < 4; gi++) {
            int row = gi * 16 + ep_c;
            float ssum = zxs[(s & 1) * 1024 + row * 16 + ep_b];
            #pragma unroll
            for (int q = 0; q < 8; q++)
                ssum += zsp[(q * 64 + row) * 16 + ep_b];
            z[gi] = ssum;
        }
        float fg = sigf(z[0]), ig = sigf(z[1]), ug = tanhf(z[2]), og = sigf(z[3]);
        creg = fg * creg + ig * ug;
        float hv = og * tanhf(creg);
        hlast = hv;
        g_hG[bg][(s + 1) & 1][(c0 + ep_c) * 16 + ep_b] = hv;
        out[((size_t)s * BB + bg * 16 + ep_b) * HH + c0 + ep_c] = hv;

        group_barrier(bcnt, bgen, 32);
    }

    size_t TBH = (size_t)TT * BB * HH;
    if ((size_t)out_size >= TBH + 2 * (size_t)BB * HH) {
        size_t bglob = (size_t)bg * 16 + ep_b;
        out[TBH + bglob * HH + c0 + ep_c] = hlast;
        out[TBH + (size_t)BB * HH + bglob * HH + c0 + ep_c] = creg;
    }
}

extern "C" void kernel_launch(void* const* d_in, const int* in_sizes, int n_in,
                              void* d_out, int out_size) {
    const float* X  = (const float*)d_in[0];
    const float* v  = (const float*)d_in[1];
    const float* g  = (const float*)d_in[2];
    const float* b  = (const float*)d_in[3];
    float* out = (float*)d_out;

    cudaFuncSetAttribute(qlstm_recur, cudaFuncAttributeMaxDynamicSharedMemorySize, SM_BYTES);

    qlstm_wnorm<<<GG, 256>>>(v, g);
    qlstm_gemm_x<<<dim3(GG / 128, TT / 2), 256>>>(X, b);
    qlstm_recur<<<P3_NCTA, 256, SM_BYTES>>>(out, out_size);
}